// round 2
// baseline (speedup 1.0000x reference)
#include <cuda_runtime.h>

#define TILE 32
#define HALO 5
#define IN_T (TILE + 2 * HALO)   // 42
#define IN_PAD 44                // padded stride for the input tiles
#define CROPPED 504
#define BATCH 16
#define NTILES 16                // ceil(504/32)

__device__ double g_acc;

__global__ void zero_acc_kernel() { g_acc = 0.0; }

__global__ __launch_bounds__(256) void ssim_main_kernel(
    const float* __restrict__ img1, const float* __restrict__ img2)
{
    __shared__ float x1s[IN_T][IN_PAD];
    __shared__ float x2s[IN_T][IN_PAD];
    __shared__ float h1 [IN_T][TILE];
    __shared__ float h2 [IN_T][TILE];
    __shared__ float h11[IN_T][TILE];
    __shared__ float h22[IN_T][TILE];
    __shared__ float h12[IN_T][TILE];

    const int b   = blockIdx.z;
    const int tj0 = blockIdx.x * TILE;
    const int ti0 = blockIdx.y * TILE;
    const int tid = threadIdx.x;

    // channel 0 of batch b is a contiguous 512x512 block
    const size_t base = (size_t)b * 3u * 512u * 512u;

    // ---- Phase 1: load 42x42 halo tiles of both images (crop offset +4) ----
    for (int idx = tid; idx < IN_T * IN_T; idx += 256) {
        const int r = idx / IN_T;
        const int c = idx - r * IN_T;
        const int gi = ti0 - HALO + r;
        const int gj = tj0 - HALO + c;
        float v1 = 0.0f, v2 = 0.0f;
        if (gi >= 0 && gi < CROPPED && gj >= 0 && gj < CROPPED) {
            const size_t off = base + (size_t)(gi + 4) * 512u + (size_t)(gj + 4);
            v1 = img1[off];
            v2 = img2[off];
        }
        x1s[r][c] = v1;
        x2s[r][c] = v2;
    }
    __syncthreads();

    // ---- Phase 2: horizontal 11-tap pass for the 5 quantities ----
    for (int idx = tid; idx < IN_T * TILE; idx += 256) {
        const int r = idx >> 5;         // idx / 32
        const int c = idx & 31;         // idx % 32
        float s1 = 0.f, s2 = 0.f, s11 = 0.f, s22 = 0.f, s12 = 0.f;
        #pragma unroll
        for (int k = 0; k < 11; k++) {
            const float a = x1s[r][c + k];
            const float bb = x2s[r][c + k];
            s1 += a;
            s2 += bb;
            s11 = fmaf(a,  a,  s11);
            s22 = fmaf(bb, bb, s22);
            s12 = fmaf(a,  bb, s12);
        }
        h1 [r][c] = s1;
        h2 [r][c] = s2;
        h11[r][c] = s11;
        h22[r][c] = s22;
        h12[r][c] = s12;
    }
    __syncthreads();

    // ---- Phase 3: vertical 11-tap pass + pointwise SSIM + local sum ----
    const float C1  = 6.5025f;     // (0.01*255)^2
    const float C2  = 58.5225f;    // (0.03*255)^2
    const float inv = 1.0f / 121.0f;

    float local = 0.0f;
    for (int idx = tid; idx < TILE * TILE; idx += 256) {
        const int i = idx >> 5;
        const int j = idx & 31;
        if (ti0 + i >= CROPPED || tj0 + j >= CROPPED) continue;

        float S1 = 0.f, S2 = 0.f, S11 = 0.f, S22 = 0.f, S12 = 0.f;
        #pragma unroll
        for (int k = 0; k < 11; k++) {
            S1  += h1 [i + k][j];
            S2  += h2 [i + k][j];
            S11 += h11[i + k][j];
            S22 += h22[i + k][j];
            S12 += h12[i + k][j];
        }
        const float mu1  = S1 * inv;
        const float mu2  = S2 * inv;
        const float mu1s = mu1 * mu1;
        const float mu2s = mu2 * mu2;
        const float mu12 = mu1 * mu2;
        const float sg1  = S11 * inv - mu1s;
        const float sg2  = S22 * inv - mu2s;
        const float sg12 = S12 * inv - mu12;
        const float num  = (2.0f * mu12 + C1) * (2.0f * sg12 + C2);
        const float den  = (mu1s + mu2s + C1) * (sg1 + sg2 + C2);
        local += __fdividef(num, den);
    }

    // ---- Block reduction: warp shfl, then cross-warp, one double atomic ----
    #pragma unroll
    for (int o = 16; o > 0; o >>= 1)
        local += __shfl_down_sync(0xffffffffu, local, o);

    __shared__ float warpsum[8];
    if ((tid & 31) == 0) warpsum[tid >> 5] = local;
    __syncthreads();
    if (tid < 8) {
        float v = warpsum[tid];
        #pragma unroll
        for (int o = 4; o > 0; o >>= 1)
            v += __shfl_down_sync(0x000000ffu, v, o);
        if (tid == 0) atomicAdd(&g_acc, (double)v);
    }
}

__global__ void finalize_kernel(float* __restrict__ out) {
    out[0] = (float)(g_acc / ((double)BATCH * CROPPED * CROPPED));
}

extern "C" void kernel_launch(void* const* d_in, const int* in_sizes, int n_in,
                              void* d_out, int out_size)
{
    const float* img1 = (const float*)d_in[0];
    const float* img2 = (const float*)d_in[1];
    float* out = (float*)d_out;

    zero_acc_kernel<<<1, 1>>>();
    dim3 grid(NTILES, NTILES, BATCH);
    ssim_main_kernel<<<grid, 256>>>(img1, img2);
    finalize_kernel<<<1, 1>>>(out);
}

// round 4
// speedup vs baseline: 3.2928x; 3.2928x over previous
#include <cuda_runtime.h>

#define IMG      512
#define CROPPED  504
#define BATCH    16
#define TILE_W   32
#define TILE_H   64
#define VW       42          // TILE_W + 10 columns in the v arrays
#define VH       64          // TILE_H rows
#define VSTRIDE  43          // padded (odd) stride -> conflict-free banks
#define NCHUNKS  6
#define CHUNK    11          // 6*11 = 66 >= 64 rows covered
#define NTX      16          // ceil(504/32)
#define NTY      8           // ceil(504/64)

__device__ double g_acc;     // zero-initialized at module load; finalize resets it

__global__ __launch_bounds__(256) void ssim_main_kernel(
    const float* __restrict__ img1, const float* __restrict__ img2)
{
    // 4 quantities: S1, S2, (S11+S22), S12  -- vertical 11-row sums
    __shared__ float v1 [VH][VSTRIDE];
    __shared__ float v2 [VH][VSTRIDE];
    __shared__ float vA [VH][VSTRIDE];
    __shared__ float v12[VH][VSTRIDE];

    const int b   = blockIdx.z;
    const int tj0 = blockIdx.x * TILE_W;
    const int ti0 = blockIdx.y * TILE_H;
    const int tid = threadIdx.x;

    const size_t base = (size_t)b * 3u * IMG * IMG;   // channel 0 of batch b

    // ================= Phase A: vertical sliding pass (gmem -> smem) =======
    // thread (c, chunk): column c of the v tile, 11-row chunk, running sums.
    if (tid < VW * NCHUNKS) {
        const int c     = tid % VW;
        const int chunk = tid / VW;
        const int r0    = chunk * CHUNK;
        const int gj    = tj0 - 5 + c;                 // cropped-coords column
        const bool colok = (unsigned)gj < (unsigned)CROPPED;
        const float* p1 = img1 + base + (gj + 4);
        const float* p2 = img2 + base + (gj + 4);

        float s1 = 0.f, s2 = 0.f, sA = 0.f, s12 = 0.f;

        // initial 11-row window for v[r0]
        #pragma unroll
        for (int k = 0; k < 11; k++) {
            const int gi = ti0 + r0 - 5 + k;
            const bool ok = colok && ((unsigned)gi < (unsigned)CROPPED);
            const size_t roff = (size_t)(gi + 4) * IMG;
            const float a  = ok ? __ldg(p1 + roff) : 0.f;
            const float bb = ok ? __ldg(p2 + roff) : 0.f;
            s1  += a;
            s2  += bb;
            sA   = fmaf(a, a, sA);
            sA   = fmaf(bb, bb, sA);
            s12  = fmaf(a, bb, s12);
        }
        v1 [r0][c] = s1;
        v2 [r0][c] = s2;
        vA [r0][c] = sA;
        v12[r0][c] = s12;

        const int rend = (r0 + CHUNK < VH) ? (r0 + CHUNK) : VH;
        for (int r = r0 + 1; r < rend; r++) {
            const int gin = ti0 + r + 5;   // incoming row
            const int gio = ti0 + r - 6;   // outgoing row
            const bool okn = colok && ((unsigned)gin < (unsigned)CROPPED);
            const bool oko = colok && ((unsigned)gio < (unsigned)CROPPED);
            const float an = okn ? __ldg(p1 + (size_t)(gin + 4) * IMG) : 0.f;
            const float bn = okn ? __ldg(p2 + (size_t)(gin + 4) * IMG) : 0.f;
            const float ao = oko ? __ldg(p1 + (size_t)(gio + 4) * IMG) : 0.f;
            const float bo = oko ? __ldg(p2 + (size_t)(gio + 4) * IMG) : 0.f;
            s1  += an - ao;
            s2  += bn - bo;
            sA  += fmaf(an, an, bn * bn) - fmaf(ao, ao, bo * bo);
            s12 += an * bn - ao * bo;
            v1 [r][c] = s1;
            v2 [r][c] = s2;
            vA [r][c] = sA;
            v12[r][c] = s12;
        }
    }
    __syncthreads();

    // ================= Phase B: horizontal sliding + SSIM ==================
    // thread (row i, 8-col segment): 64 rows x 4 segments = 256 threads.
    const float C1   = 6.5025f;                // (0.01*255)^2
    const float C2   = 58.5225f;               // (0.03*255)^2
    const float inv  = 1.0f / 121.0f;
    const float SCL  = 1.52587890625e-5f;      // 2^-16

    float local = 0.0f;
    {
        const int i   = tid >> 2;              // 0..63
        const int seg = tid & 3;
        const int j0  = seg * 8;

        if (ti0 + i < CROPPED) {
            float S1 = 0.f, S2 = 0.f, SA = 0.f, S12 = 0.f;
            #pragma unroll
            for (int k = 0; k < 11; k++) {
                S1  += v1 [i][j0 + k];
                S2  += v2 [i][j0 + k];
                SA  += vA [i][j0 + k];
                S12 += v12[i][j0 + k];
            }

            float n[8], d[8];
            #pragma unroll
            for (int t = 0; t < 8; t++) {
                const int j = j0 + t;
                if (tj0 + j < CROPPED) {
                    const float mu1  = S1 * inv;
                    const float mu2  = S2 * inv;
                    const float m1s  = mu1 * mu1;
                    const float m2s  = mu2 * mu2;
                    const float m12  = mu1 * mu2;
                    const float sgA  = SA  * inv - m1s - m2s;  // sigma1^2+sigma2^2
                    const float sg12 = S12 * inv - m12;
                    const float num  = (2.0f * m12 + C1) * (2.0f * sg12 + C2);
                    const float den  = (m1s + m2s + C1) * (sgA + C2);
                    n[t] = num * SCL;
                    d[t] = den * SCL;
                } else {
                    n[t] = 0.0f;
                    d[t] = 1.0f;
                }
                if (t < 7) {   // slide window: add col j+11, drop col j
                    S1  += v1 [i][j + 11] - v1 [i][j];
                    S2  += v2 [i][j + 11] - v2 [i][j];
                    SA  += vA [i][j + 11] - vA [i][j];
                    S12 += v12[i][j + 11] - v12[i][j];
                }
            }

            // 4-way ratio combine: one MUFU rcp per 4 pixels
            #pragma unroll
            for (int g = 0; g < 2; g++) {
                const int o = g * 4;
                const float n12 = n[o+0] * d[o+1] + n[o+1] * d[o+0];
                const float d12 = d[o+0] * d[o+1];
                const float n34 = n[o+2] * d[o+3] + n[o+3] * d[o+2];
                const float d34 = d[o+2] * d[o+3];
                const float N   = n12 * d34 + n34 * d12;
                const float D   = d12 * d34;
                local += __fdividef(N, D);
            }
        }
    }

    // ================= Block reduction -> one double atomic =================
    #pragma unroll
    for (int o = 16; o > 0; o >>= 1)
        local += __shfl_down_sync(0xffffffffu, local, o);

    __shared__ float warpsum[8];
    if ((tid & 31) == 0) warpsum[tid >> 5] = local;
    __syncthreads();
    if (tid < 8) {
        float v = warpsum[tid];
        #pragma unroll
        for (int o = 4; o > 0; o >>= 1)
            v += __shfl_down_sync(0x000000ffu, v, o);
        if (tid == 0) atomicAdd(&g_acc, (double)v);
    }
}

__global__ void finalize_kernel(float* __restrict__ out) {
    out[0] = (float)(g_acc / ((double)BATCH * CROPPED * CROPPED));
    g_acc = 0.0;   // self-reset: next call starts from zero (deterministic)
}

extern "C" void kernel_launch(void* const* d_in, const int* in_sizes, int n_in,
                              void* d_out, int out_size)
{
    const float* img1 = (const float*)d_in[0];
    const float* img2 = (const float*)d_in[1];
    float* out = (float*)d_out;

    dim3 grid(NTX, NTY, BATCH);
    ssim_main_kernel<<<grid, 256>>>(img1, img2);
    finalize_kernel<<<1, 1>>>(out);
}

// round 5
// speedup vs baseline: 3.7917x; 1.1515x over previous
#include <cuda_runtime.h>

#define IMG      512
#define CROPPED  504
#define BATCH    16
#define TILE_W   32
#define TILE_H   64
#define VW       42          // TILE_W + 10 columns in the v arrays
#define VH       64          // TILE_H rows
#define VSTRIDE  43          // padded (odd) stride -> conflict-free banks
#define NCHUNKS  6
#define CHUNK    11          // 6*11 = 66 >= 64 rows covered (tail predicated)
#define NTX      16          // ceil(504/32)
#define NTY      8           // ceil(504/64)
#define TOTAL_CTAS (NTX * NTY * BATCH)

__device__ double   g_acc;    // zero at module load; last block resets each call
__device__ unsigned g_count;  // completion counter, ditto

__global__ __launch_bounds__(256) void ssim_main_kernel(
    const float* __restrict__ img1, const float* __restrict__ img2,
    float* __restrict__ out)
{
    // 4 vertical 11-row running sums: S1, S2, (S11+S22), S12
    __shared__ float v1 [VH][VSTRIDE];
    __shared__ float v2 [VH][VSTRIDE];
    __shared__ float vA [VH][VSTRIDE];
    __shared__ float v12[VH][VSTRIDE];

    const int b   = blockIdx.z;
    const int tj0 = blockIdx.x * TILE_W;
    const int ti0 = blockIdx.y * TILE_H;
    const int tid = threadIdx.x;

    const size_t base = (size_t)b * 3u * IMG * IMG;   // channel 0 of batch b

    // ================= Phase A: vertical sliding pass (gmem -> smem) =======
    // thread (c, chunk): column c, 11-row chunk. The 11-deep input window is
    // kept in registers so slides only load the incoming row (2 LDG not 4).
    if (tid < VW * NCHUNKS) {
        const int c     = tid % VW;
        const int chunk = tid / VW;
        const int r0    = chunk * CHUNK;
        const int gj    = tj0 - 5 + c;
        const bool colok = (unsigned)gj < (unsigned)CROPPED;
        const float* p1 = img1 + base + (gj + 4);
        const float* p2 = img2 + base + (gj + 4);

        float a_w[CHUNK], b_w[CHUNK];
        float s1 = 0.f, s2 = 0.f, sA = 0.f, s12 = 0.f;

        // initial 11-row window for v[r0] (loads batch-issued: high MLP)
        #pragma unroll
        for (int k = 0; k < 11; k++) {
            const int gi = ti0 + r0 - 5 + k;
            const bool ok = colok && ((unsigned)gi < (unsigned)CROPPED);
            const size_t roff = (size_t)(gi + 4) * IMG;
            const float a  = ok ? __ldg(p1 + roff) : 0.f;
            const float bb = ok ? __ldg(p2 + roff) : 0.f;
            a_w[k] = a;
            b_w[k] = bb;
            s1  += a;
            s2  += bb;
            sA   = fmaf(a, a, fmaf(bb, bb, sA));
            s12  = fmaf(a, bb, s12);
        }
        v1 [r0][c] = s1;
        v2 [r0][c] = s2;
        vA [r0][c] = sA;
        v12[r0][c] = s12;

        #pragma unroll
        for (int t = 1; t < CHUNK; t++) {
            const int r = r0 + t;
            if (r < VH) {
                const int gin = ti0 + r + 5;                 // incoming row
                const bool okn = colok && ((unsigned)gin < (unsigned)CROPPED);
                const float an = okn ? __ldg(p1 + (size_t)(gin + 4) * IMG) : 0.f;
                const float bn = okn ? __ldg(p2 + (size_t)(gin + 4) * IMG) : 0.f;
                const float ao = a_w[t - 1];                 // outgoing from regs
                const float bo = b_w[t - 1];
                s1  += an - ao;
                s2  += bn - bo;
                sA  += fmaf(an, an, bn * bn) - fmaf(ao, ao, bo * bo);
                s12 += an * bn - ao * bo;
                v1 [r][c] = s1;
                v2 [r][c] = s2;
                vA [r][c] = sA;
                v12[r][c] = s12;
            }
        }
    }
    __syncthreads();

    // ================= Phase B: horizontal sliding + SSIM ==================
    const float C1   = 6.5025f;                // (0.01*255)^2
    const float C2   = 58.5225f;               // (0.03*255)^2
    const float inv  = 1.0f / 121.0f;
    const float SCL  = 1.52587890625e-5f;      // 2^-16 pre-scale (no overflow)

    float local = 0.0f;
    {
        const int i   = tid >> 2;              // row 0..63
        const int seg = tid & 3;
        const int j0  = seg * 8;

        if (ti0 + i < CROPPED) {
            float S1 = 0.f, S2 = 0.f, SA = 0.f, S12 = 0.f;
            #pragma unroll
            for (int k = 0; k < 11; k++) {
                S1  += v1 [i][j0 + k];
                S2  += v2 [i][j0 + k];
                SA  += vA [i][j0 + k];
                S12 += v12[i][j0 + k];
            }

            float n[8], d[8];
            #pragma unroll
            for (int t = 0; t < 8; t++) {
                const int j = j0 + t;
                if (tj0 + j < CROPPED) {
                    const float mu1  = S1 * inv;
                    const float mu2  = S2 * inv;
                    const float m1s  = mu1 * mu1;
                    const float m2s  = mu2 * mu2;
                    const float m12  = mu1 * mu2;
                    const float sgA  = SA  * inv - m1s - m2s;  // sig1^2+sig2^2
                    const float sg12 = S12 * inv - m12;
                    const float num  = (2.0f * m12 + C1) * (2.0f * sg12 + C2);
                    const float den  = (m1s + m2s + C1) * (sgA + C2);
                    n[t] = num * SCL;
                    d[t] = den * SCL;
                } else {
                    n[t] = 0.0f;
                    d[t] = 1.0f;
                }
                if (t < 7) {   // slide: add col j+11, drop col j
                    S1  += v1 [i][j + 11] - v1 [i][j];
                    S2  += v2 [i][j + 11] - v2 [i][j];
                    SA  += vA [i][j + 11] - vA [i][j];
                    S12 += v12[i][j + 11] - v12[i][j];
                }
            }

            // 4-way ratio combine: one MUFU rcp per 4 pixels
            #pragma unroll
            for (int g = 0; g < 2; g++) {
                const int o = g * 4;
                const float n12 = n[o+0] * d[o+1] + n[o+1] * d[o+0];
                const float d12 = d[o+0] * d[o+1];
                const float n34 = n[o+2] * d[o+3] + n[o+3] * d[o+2];
                const float d34 = d[o+2] * d[o+3];
                const float N   = n12 * d34 + n34 * d12;
                const float D   = d12 * d34;
                local += __fdividef(N, D);
            }
        }
    }

    // ================= Block reduction -> one double atomic =================
    #pragma unroll
    for (int o = 16; o > 0; o >>= 1)
        local += __shfl_down_sync(0xffffffffu, local, o);

    __shared__ float warpsum[8];
    if ((tid & 31) == 0) warpsum[tid >> 5] = local;
    __syncthreads();

    if (tid == 0) {
        float v = warpsum[0];
        #pragma unroll
        for (int w = 1; w < 8; w++) v += warpsum[w];
        atomicAdd(&g_acc, (double)v);

        // ---- last-CTA finalize (replaces the second kernel launch) ----
        __threadfence();
        const unsigned ticket = atomicAdd(&g_count, 1u);
        if (ticket == TOTAL_CTAS - 1) {
            const double acc = g_acc;
            out[0] = (float)(acc / ((double)BATCH * CROPPED * CROPPED));
            g_acc   = 0.0;   // reset for the next graph replay
            g_count = 0u;
            __threadfence();
        }
    }
}

extern "C" void kernel_launch(void* const* d_in, const int* in_sizes, int n_in,
                              void* d_out, int out_size)
{
    const float* img1 = (const float*)d_in[0];
    const float* img2 = (const float*)d_in[1];
    float* out = (float*)d_out;

    dim3 grid(NTX, NTY, BATCH);
    ssim_main_kernel<<<grid, 256>>>(img1, img2, out);
}

// round 6
// speedup vs baseline: 3.8949x; 1.0272x over previous
#include <cuda_runtime.h>

#define IMG      512
#define CROPPED  504
#define BATCH    16
#define TILE_W   32
#define TILE_H   64
#define VW       42          // TILE_W + 10 columns in the v arrays
#define VH       64          // TILE_H rows
#define VSTRIDE  43          // odd stride -> conflict-free bank groups
#define NCHUNKS  6
#define CHUNK    11          // 6*11 = 66 >= 64 rows (tail predicated)
#define NTX      16          // ceil(504/32)
#define NTY      8           // ceil(504/64)
#define TOTAL_CTAS (NTX * NTY * BATCH)

__device__ double   g_acc;    // zero at module load; last CTA resets each call
__device__ unsigned g_count;

__global__ __launch_bounds__(256) void ssim_main_kernel(
    const float* __restrict__ img1, const float* __restrict__ img2,
    float* __restrict__ out)
{
    // packed vertical 11-row running sums: {S1, S2, S11+S22, S12}
    __shared__ float4 vv[VH][VSTRIDE];

    const int b   = blockIdx.z;
    const int tj0 = blockIdx.x * TILE_W;
    const int ti0 = blockIdx.y * TILE_H;
    const int tid = threadIdx.x;

    const size_t base = (size_t)b * 3u * IMG * IMG;   // channel 0 of batch b

    // ================= Phase A: vertical sliding pass (gmem -> smem) =======
    // thread (c, chunk): column c, 11-row chunk; 11-deep window in registers.
    if (tid < VW * NCHUNKS) {
        const int c     = tid % VW;
        const int chunk = tid / VW;
        const int r0    = chunk * CHUNK;
        const int gj    = tj0 - 5 + c;
        const bool colok = (unsigned)gj < (unsigned)CROPPED;
        const float* p1 = img1 + base + (gj + 4);
        const float* p2 = img2 + base + (gj + 4);

        float a_w[CHUNK], b_w[CHUNK];
        float s1 = 0.f, s2 = 0.f, sA = 0.f, s12 = 0.f;

        #pragma unroll
        for (int k = 0; k < 11; k++) {
            const int gi = ti0 + r0 - 5 + k;
            const bool ok = colok && ((unsigned)gi < (unsigned)CROPPED);
            const size_t roff = (size_t)(gi + 4) * IMG;
            const float a  = ok ? __ldg(p1 + roff) : 0.f;
            const float bb = ok ? __ldg(p2 + roff) : 0.f;
            a_w[k] = a;
            b_w[k] = bb;
            s1  += a;
            s2  += bb;
            sA   = fmaf(a, a, fmaf(bb, bb, sA));
            s12  = fmaf(a, bb, s12);
        }
        vv[r0][c] = make_float4(s1, s2, sA, s12);

        #pragma unroll
        for (int t = 1; t < CHUNK; t++) {
            const int r = r0 + t;
            if (r < VH) {
                const int gin = ti0 + r + 5;                 // incoming row
                const bool okn = colok && ((unsigned)gin < (unsigned)CROPPED);
                const float an = okn ? __ldg(p1 + (size_t)(gin + 4) * IMG) : 0.f;
                const float bn = okn ? __ldg(p2 + (size_t)(gin + 4) * IMG) : 0.f;
                const float ao = a_w[t - 1];                 // outgoing from regs
                const float bo = b_w[t - 1];
                s1  += an - ao;
                s2  += bn - bo;
                sA  += fmaf(an, an, bn * bn) - fmaf(ao, ao, bo * bo);
                s12 += an * bn - ao * bo;
                vv[r][c] = make_float4(s1, s2, sA, s12);
            }
        }
    }
    __syncthreads();

    // ================= Phase B: horizontal sliding + SSIM ==================
    // mapping (i = tid&63, seg = tid>>6): 8 consecutive rows per quarter-warp
    // -> bank-group (3i+j) mod 8 distinct -> conflict-free LDS.128.
    const float C1   = 6.5025f;                // (0.01*255)^2
    const float C2   = 58.5225f;               // (0.03*255)^2
    const float inv  = 1.0f / 121.0f;
    const float SCL  = 1.52587890625e-5f;      // 2^-16 pre-scale

    float local = 0.0f;
    {
        const int i   = tid & 63;              // row 0..63
        const int seg = tid >> 6;              // 0..3
        const int j0  = seg * 8;

        if (ti0 + i < CROPPED) {
            float S1 = 0.f, S2 = 0.f, SA = 0.f, S12 = 0.f;
            #pragma unroll
            for (int k = 0; k < 11; k++) {
                const float4 t = vv[i][j0 + k];
                S1  += t.x;
                S2  += t.y;
                SA  += t.z;
                S12 += t.w;
            }

            float n[8], d[8];
            #pragma unroll
            for (int t = 0; t < 8; t++) {
                const int j = j0 + t;
                if (tj0 + j < CROPPED) {
                    const float mu1  = S1 * inv;
                    const float mu2  = S2 * inv;
                    const float m1s  = mu1 * mu1;
                    const float m2s  = mu2 * mu2;
                    const float m12  = mu1 * mu2;
                    const float sgA  = SA  * inv - m1s - m2s;  // sig1^2+sig2^2
                    const float sg12 = S12 * inv - m12;
                    const float num  = (2.0f * m12 + C1) * (2.0f * sg12 + C2);
                    const float den  = (m1s + m2s + C1) * (sgA + C2);
                    n[t] = num * SCL;
                    d[t] = den * SCL;
                } else {
                    n[t] = 0.0f;
                    d[t] = 1.0f;
                }
                if (t < 7) {   // slide: add col j+11, drop col j
                    const float4 va = vv[i][j + 11];
                    const float4 vs = vv[i][j];
                    S1  += va.x - vs.x;
                    S2  += va.y - vs.y;
                    SA  += va.z - vs.z;
                    S12 += va.w - vs.w;
                }
            }

            // 4-way ratio combine: one MUFU rcp per 4 pixels
            #pragma unroll
            for (int g = 0; g < 2; g++) {
                const int o = g * 4;
                const float n12 = n[o+0] * d[o+1] + n[o+1] * d[o+0];
                const float d12 = d[o+0] * d[o+1];
                const float n34 = n[o+2] * d[o+3] + n[o+3] * d[o+2];
                const float d34 = d[o+2] * d[o+3];
                const float N   = n12 * d34 + n34 * d12;
                const float D   = d12 * d34;
                local += __fdividef(N, D);
            }
        }
    }

    // ================= Block reduction -> one double atomic =================
    #pragma unroll
    for (int o = 16; o > 0; o >>= 1)
        local += __shfl_down_sync(0xffffffffu, local, o);

    __shared__ float warpsum[8];
    if ((tid & 31) == 0) warpsum[tid >> 5] = local;
    __syncthreads();

    if (tid == 0) {
        float v = warpsum[0];
        #pragma unroll
        for (int w = 1; w < 8; w++) v += warpsum[w];
        atomicAdd(&g_acc, (double)v);

        // ---- last-CTA finalize ----
        __threadfence();
        const unsigned ticket = atomicAdd(&g_count, 1u);
        if (ticket == TOTAL_CTAS - 1) {
            const double acc = g_acc;
            out[0] = (float)(acc / ((double)BATCH * CROPPED * CROPPED));
            g_acc   = 0.0;   // reset for next graph replay
            g_count = 0u;
            __threadfence();
        }
    }
}

extern "C" void kernel_launch(void* const* d_in, const int* in_sizes, int n_in,
                              void* d_out, int out_size)
{
    const float* img1 = (const float*)d_in[0];
    const float* img2 = (const float*)d_in[1];
    float* out = (float*)d_out;

    dim3 grid(NTX, NTY, BATCH);
    ssim_main_kernel<<<grid, 256>>>(img1, img2, out);
}